// round 13
// baseline (speedup 1.0000x reference)
#include <cuda_runtime.h>
#include <cstdint>

#define B_    32
#define T_    4096
#define D_    256
#define H_    256
#define G4_   1024
#define HOR_  24

typedef unsigned long long ull;

// ---------------- device scratch (static; no runtime allocation) ----------------
__device__ __align__(16) float g_XG[(size_t)B_ * T_ * G4_];   // [m=b*T+t][n] fp32, 512 MB
__device__ __align__(16) float g_h[B_ * H_];                  // final hidden state [b][j]

// ---------------- helpers ----------------
__device__ __forceinline__ ull pack2(float x, float y) {
    ull r;
    asm("mov.b64 %0, {%1, %2};" : "=l"(r) : "f"(x), "f"(y));
    return r;
}
__device__ __forceinline__ void unpack2(ull v, float& x, float& y) {
    asm("mov.b64 {%0, %1}, %2;" : "=f"(x), "=f"(y) : "l"(v));
}
__device__ __forceinline__ ull fma2(ull a, ull w, ull x) {
    asm("fma.rn.f32x2 %0, %1, %2, %0;" : "+l"(a) : "l"(w), "l"(x));
    return a;
}
__device__ __forceinline__ float ex2f(float x) {
    float y; asm("ex2.approx.f32 %0, %1;" : "=f"(y) : "f"(x)); return y;
}
__device__ __forceinline__ float rcpf(float x) {
    float y; asm("rcp.approx.f32 %0, %1;" : "=f"(y) : "f"(x)); return y;
}
__device__ __forceinline__ float sigf(float x) {
    return rcpf(1.f + ex2f(-1.4426950408889634f * x));
}
__device__ __forceinline__ float tanh_f(float x) {
    return fmaf(2.f, rcpf(1.f + ex2f(-2.8853900817779268f * x)), -1.f);
}
__device__ __forceinline__ unsigned smem_u32(const void* p) {
    return (unsigned)__cvta_generic_to_shared(p);
}
__device__ __forceinline__ void mbar_wait_cluster(unsigned mb, unsigned par) {
    asm volatile(
        "{\n\t"
        ".reg .pred P;\n\t"
        "WL_%=:\n\t"
        "mbarrier.try_wait.parity.acquire.cluster.shared::cta.b64 P, [%0], %1, 0x989680;\n\t"
        "@!P bra WL_%=;\n\t"
        "}"
        :: "r"(mb), "r"(par) : "memory");
}

// ---------------- kernel 1: SGEMM  XG[m][n] = A[m][k] @ W[k][n] + bl[n] ----------------
// (R5 version: best measured — 76 regs, occ 37%, fma 63%.)
// M=131072, N=1024, K=256. Tile 128M x 64N, K-tile 16, double-buffered.
#define MT 128
#define NT 64
#define KT 16

__global__ void __launch_bounds__(256) k_xgemm(const float* __restrict__ A,
                                               const float* __restrict__ W,
                                               const float* __restrict__ bl) {
    __shared__ __align__(16) float As[2][KT][MT];
    __shared__ __align__(16) float Bs[2][KT][NT];
    const int tid = threadIdx.x;
    const int m0 = blockIdx.x * MT;
    const int n0 = blockIdx.y * NT;

    const int ar0 = tid >> 2;
    const int akc = (tid & 3) * 4;
    const int bk = tid >> 4;
    const int bn = (tid & 15) * 4;
    const int mt = tid >> 4;
    const int nt = tid & 15;

    const float* Ar0 = A + (size_t)(m0 + ar0) * D_ + akc;
    const float* Ar1 = A + (size_t)(m0 + 64 + ar0) * D_ + akc;
    const float* Wp  = W + (size_t)bk * G4_ + n0 + bn;

    float4 a0 = *(const float4*)(Ar0);
    float4 a1 = *(const float4*)(Ar1);
    float4 b0 = *(const float4*)(Wp);
    #pragma unroll
    for (int i = 0; i < 4; i++) {
        As[0][akc + i][ar0]      = ((const float*)&a0)[i];
        As[0][akc + i][64 + ar0] = ((const float*)&a1)[i];
    }
    *(float4*)&Bs[0][bk][bn] = b0;
    __syncthreads();

    ull acc[4][4];
    #pragma unroll
    for (int p = 0; p < 4; p++)
        #pragma unroll
        for (int n = 0; n < 4; n++) acc[p][n] = 0ull;

    #pragma unroll 1
    for (int kt = 0; kt < D_ / KT; kt++) {
        const int cur = kt & 1, nxt = cur ^ 1;
        if (kt + 1 < D_ / KT) {
            a0 = *(const float4*)(Ar0 + (kt + 1) * KT);
            a1 = *(const float4*)(Ar1 + (kt + 1) * KT);
            b0 = *(const float4*)(Wp + (size_t)(kt + 1) * KT * G4_);
        }
        #pragma unroll
        for (int k = 0; k < KT; k++) {
            const ull* ap = (const ull*)&As[cur][k][mt * 8];
            const float* bp = &Bs[cur][k][nt * 4];
            ull am0 = ap[0], am1 = ap[1], am2 = ap[2], am3 = ap[3];
            #pragma unroll
            for (int n = 0; n < 4; n++) {
                ull bb = pack2(bp[n], bp[n]);
                acc[0][n] = fma2(acc[0][n], am0, bb);
                acc[1][n] = fma2(acc[1][n], am1, bb);
                acc[2][n] = fma2(acc[2][n], am2, bb);
                acc[3][n] = fma2(acc[3][n], am3, bb);
            }
        }
        if (kt + 1 < D_ / KT) {
            #pragma unroll
            for (int i = 0; i < 4; i++) {
                As[nxt][akc + i][ar0]      = ((const float*)&a0)[i];
                As[nxt][akc + i][64 + ar0] = ((const float*)&a1)[i];
            }
            *(float4*)&Bs[nxt][bk][bn] = b0;
            __syncthreads();
        }
    }

    float bias[4];
    #pragma unroll
    for (int n = 0; n < 4; n++) bias[n] = bl[n0 + nt * 4 + n];
    float* Cr = g_XG + (size_t)(m0 + mt * 8) * G4_ + n0 + nt * 4;
    #pragma unroll
    for (int p = 0; p < 4; p++) {
        float e[4], o[4];
        #pragma unroll
        for (int n = 0; n < 4; n++) {
            unpack2(acc[p][n], e[n], o[n]);
            e[n] += bias[n]; o[n] += bias[n];
        }
        *(float4*)(Cr + (size_t)(2 * p) * G4_)     = make_float4(e[0], e[1], e[2], e[3]);
        *(float4*)(Cr + (size_t)(2 * p + 1) * G4_) = make_float4(o[0], o[1], o[2], o[3]);
    }
}

// ---------------- kernel 2: clustered LSTM recurrence ----------------
// 32 clusters x 8 CTAs, occ 2. Cluster g = batch g. CTA rank r owns j in [32r, 32r+32).
// Thread (w = tid>>5, l = tid&31): K-chunk [32w, 32w+32), hidden j = 32r + l, 4 gates.
// Per-source mbars [src][parity]; packed float4 reduction; producer/consumer sync via
// parity-alternating named barriers (ids 1,2). xg_s staging is AFTER the mbar-wait —
// the wait's dependency chain is what protects the parity-lapped xg_s buffer from WAR.
struct RnnSmem {
    ull   Wst[8][6][4][32];    // [w][p][q][l] streamed weight pairs, 48 KB
    float red[2][8][32][4];    // [par][w][l][q] packed partials, 8 KB
    float hs[2][H_];           // [parity][j] hidden state, 2 KB
    float xg_s[2][32][4];      // [par][l][q] staged XG (float4 read), 1 KB
    ull   mbar[16];            // [src*2 + parity]
};

__global__ void __launch_bounds__(256, 2) __cluster_dims__(8, 1, 1)
k_rnn(const float* __restrict__ W) {
    extern __shared__ __align__(16) unsigned char smem_raw[];
    RnnSmem* S = (RnnSmem*)smem_raw;

    const int tid = threadIdx.x;
    const int w   = tid >> 5;
    const int l   = tid & 31;
    const int r   = blockIdx.x & 7;
    const int g   = blockIdx.x >> 3;
    const int kbase = w * 32;
    const int j   = r * 32 + l;

    // stationary weights: 40 reg pairs + 24 streamed pairs per thread
    ull wreg[40];
    #pragma unroll
    for (int q = 0; q < 4; q++) {
        int n = q * 256 + j;
        #pragma unroll
        for (int p = 0; p < 10; p++) {
            int k = kbase + 2 * p;
            wreg[q * 10 + p] = pack2(W[(size_t)(D_ + k) * G4_ + n],
                                     W[(size_t)(D_ + k + 1) * G4_ + n]);
        }
        #pragma unroll
        for (int p = 0; p < 6; p++) {
            int k = kbase + 20 + 2 * p;
            S->Wst[w][p][q][l] = pack2(W[(size_t)(D_ + k) * G4_ + n],
                                       W[(size_t)(D_ + k + 1) * G4_ + n]);
        }
    }
    for (int i = tid; i < H_; i += 256) S->hs[0][i] = 0.f;
    float c_state = 0.f;   // valid in warp 0

    const unsigned sbase  = smem_u32(S);
    const unsigned hs_off = (unsigned)((char*)&S->hs[0][0] - (char*)S);
    const unsigned mb_off = (unsigned)((char*)&S->mbar[0] - (char*)S);

    if (tid == 0) {
        #pragma unroll
        for (int i = 0; i < 16; i++) {
            asm volatile("mbarrier.init.shared.b64 [%0], 1;"
                         :: "r"(sbase + mb_off + i * 8) : "memory");
        }
        #pragma unroll
        for (int i = 0; i < 16; i++) {
            asm volatile("mbarrier.arrive.expect_tx.shared.b64 _, [%0], 128;"
                         :: "r"(sbase + mb_off + i * 8) : "memory");
        }
    }
    __syncthreads();
    asm volatile("barrier.cluster.arrive.aligned;" ::: "memory");
    asm volatile("barrier.cluster.wait.aligned;"   ::: "memory");

    unsigned rbase[8];
    #pragma unroll
    for (int d = 0; d < 8; d++)
        asm("mapa.shared::cluster.u32 %0, %1, %2;" : "=r"(rbase[d]) : "r"(sbase), "r"(d));

    const ull ONE2 = pack2(1.f, 1.f);

    // XG stream: warp w (w<4) covers gate w: XG[g][t][w*256 + j], one 128B line/warp/step
    const float* xgp = g_XG + ((size_t)g * T_) * G4_ + w * 256 + j;
    float xv = (tid < 128) ? __ldcs(xgp) : 0.f;

    #pragma unroll 1
    for (int t = 0; t < T_; ++t) {
        const int par = t & 1;

        // wait only for the source rank whose h slice this warp consumes
        if (t > 0) {
            const unsigned moff = sbase + mb_off + (unsigned)((w * 2 + ((t - 1) & 1)) * 8);
            mbar_wait_cluster(moff, ((t - 1) >> 1) & 1);
            if (l == 0) {
                asm volatile("mbarrier.arrive.expect_tx.shared.b64 _, [%0], 128;"
                             :: "r"(moff) : "memory");
            }
        }

        // stage XG (AFTER the wait: the wait's chain protects the lapped buffer) + prefetch
        if (tid < 128) {
            S->xg_s[par][l][w] = xv;
            if (t + 1 < T_) xv = __ldcs(xgp + (size_t)(t + 1) * G4_);
        }

        const ull* hp = (const ull*)&S->hs[par][kbase];
        ull acc0 = 0, acc1 = 0, acc2 = 0, acc3 = 0;

        #pragma unroll
        for (int p = 0; p < 10; p++) {
            ull h = hp[p];
            acc0 = fma2(acc0, wreg[p],      h);
            acc1 = fma2(acc1, wreg[10 + p], h);
            acc2 = fma2(acc2, wreg[20 + p], h);
            acc3 = fma2(acc3, wreg[30 + p], h);
        }
        const ull* wst = &S->Wst[w][0][0][l];
        #pragma unroll
        for (int p = 0; p < 6; p++) {
            ull h = hp[10 + p];
            acc0 = fma2(acc0, wst[p * 128 + 0],  h);
            acc1 = fma2(acc1, wst[p * 128 + 32], h);
            acc2 = fma2(acc2, wst[p * 128 + 64], h);
            acc3 = fma2(acc3, wst[p * 128 + 96], h);
        }

        // one STS.128 of this thread's 4 gate partials
        {
            float ax, ay;
            float4 rv;
            unpack2(acc0, ax, ay); rv.x = ax + ay;
            unpack2(acc1, ax, ay); rv.y = ax + ay;
            unpack2(acc2, ax, ay); rv.z = ax + ay;
            unpack2(acc3, ax, ay); rv.w = ax + ay;
            *(float4*)&S->red[par][w][l][0] = rv;
        }

        // parity-alternating named barrier: producers arrive, consumer syncs
        if (w != 0) {
            asm volatile("bar.arrive %0, 256;" :: "r"(1 + par) : "memory");
        } else {
            asm volatile("bar.sync %0, 256;" :: "r"(1 + par) : "memory");

            float4 x4 = *(const float4*)&S->xg_s[par][l][0];
            ull s01 = pack2(x4.x, x4.y);
            ull s23 = pack2(x4.z, x4.w);
            #pragma unroll
            for (int kh = 0; kh < 8; kh++) {
                float4 v = *(const float4*)&S->red[par][kh][l][0];
                s01 = fma2(s01, pack2(v.x, v.y), ONE2);
                s23 = fma2(s23, pack2(v.z, v.w), ONE2);
            }
            float gi_, gg_, gf_, go_;
            unpack2(s01, gi_, gg_);
            unpack2(s23, gf_, go_);

            c_state = sigf(gf_ + 1.f) * c_state + sigf(gi_) * tanh_f(gg_);
            float h = sigf(go_) * tanh_f(c_state);
            unsigned hbits = __float_as_uint(h);

            if (t + 1 < T_) {
                const unsigned dst_off = hs_off + (unsigned)((((t + 1) & 1) * H_ + j) * 4);
                const unsigned mbr_off = mb_off + (unsigned)((r * 2 + par) * 8);
                #pragma unroll
                for (int d = 0; d < 8; d++) {
                    asm volatile(
                        "st.async.weak.shared::cluster.mbarrier::complete_tx::bytes.u32 [%0], %1, [%2];"
                        :: "r"(rbase[d] + dst_off), "r"(hbits), "r"(rbase[d] + mbr_off)
                        : "memory");
                }
            } else {
                g_h[g * H_ + j] = h;
            }
        }
    }
    // no drain needed: every issued store is consumed by a receiver wait before exit
}

// ---------------- kernel 3: out = (h @ Wfc + bfc) @ Wout + bout ----------------
__global__ void __launch_bounds__(256) k_fc(const float* __restrict__ Wfc,
                                            const float* __restrict__ bfc,
                                            const float* __restrict__ Wout,
                                            const float* __restrict__ bout,
                                            float* __restrict__ out) {
    __shared__ float tmp[H_];
    int b = blockIdx.x;
    int jj = threadIdx.x;
    const float* h = &g_h[b * H_];
    float s = bfc[jj];
    #pragma unroll 8
    for (int k = 0; k < H_; k++) s += h[k] * Wfc[(size_t)k * H_ + jj];
    tmp[jj] = s;
    __syncthreads();
    if (jj < HOR_) {
        float o = bout[jj];
        #pragma unroll 8
        for (int k = 0; k < H_; k++) o += tmp[k] * Wout[(size_t)k * HOR_ + jj];
        out[b * HOR_ + jj] = o;
    }
}

// ---------------- launch ----------------
extern "C" void kernel_launch(void* const* d_in, const int* in_sizes, int n_in,
                              void* d_out, int out_size) {
    const float* x      = (const float*)d_in[0];
    const float* W_lstm = (const float*)d_in[1];
    const float* b_lstm = (const float*)d_in[2];
    const float* W_fc   = (const float*)d_in[3];
    const float* b_fc   = (const float*)d_in[4];
    const float* W_out  = (const float*)d_in[5];
    const float* b_out  = (const float*)d_in[6];
    float* out = (float*)d_out;

    cudaFuncSetAttribute(k_rnn, cudaFuncAttributeMaxDynamicSharedMemorySize,
                         (int)sizeof(RnnSmem));

    k_xgemm<<<dim3((B_ * T_) / MT, G4_ / NT), 256>>>(x, W_lstm, b_lstm);
    k_rnn<<<256, 256, sizeof(RnnSmem)>>>(W_lstm);
    k_fc<<<B_, 256>>>(W_fc, b_fc, W_out, b_out, out);
}

// round 14
// speedup vs baseline: 1.0748x; 1.0748x over previous
#include <cuda_runtime.h>
#include <cstdint>

#define B_    32
#define T_    4096
#define D_    256
#define H_    256
#define G4_   1024
#define HOR_  24

typedef unsigned long long ull;

// ---------------- device scratch (static; no runtime allocation) ----------------
__device__ __align__(16) float g_XG[(size_t)B_ * T_ * G4_];   // [m=b*T+t][n] fp32, 512 MB
__device__ __align__(16) float g_h[B_ * H_];                  // final hidden state [b][j]

// ---------------- helpers ----------------
__device__ __forceinline__ ull pack2(float x, float y) {
    ull r;
    asm("mov.b64 %0, {%1, %2};" : "=l"(r) : "f"(x), "f"(y));
    return r;
}
__device__ __forceinline__ void unpack2(ull v, float& x, float& y) {
    asm("mov.b64 {%0, %1}, %2;" : "=f"(x), "=f"(y) : "l"(v));
}
__device__ __forceinline__ ull fma2(ull a, ull w, ull x) {
    asm("fma.rn.f32x2 %0, %1, %2, %0;" : "+l"(a) : "l"(w), "l"(x));
    return a;
}
__device__ __forceinline__ float ex2f(float x) {
    float y; asm("ex2.approx.f32 %0, %1;" : "=f"(y) : "f"(x)); return y;
}
__device__ __forceinline__ float rcpf(float x) {
    float y; asm("rcp.approx.f32 %0, %1;" : "=f"(y) : "f"(x)); return y;
}
__device__ __forceinline__ float sigf(float x) {
    return rcpf(1.f + ex2f(-1.4426950408889634f * x));
}
__device__ __forceinline__ float tanh_f(float x) {
    return fmaf(2.f, rcpf(1.f + ex2f(-2.8853900817779268f * x)), -1.f);
}
__device__ __forceinline__ unsigned smem_u32(const void* p) {
    return (unsigned)__cvta_generic_to_shared(p);
}
__device__ __forceinline__ void mbar_wait_cluster(unsigned mb, unsigned par) {
    asm volatile(
        "{\n\t"
        ".reg .pred P;\n\t"
        "WL_%=:\n\t"
        "mbarrier.try_wait.parity.acquire.cluster.shared::cta.b64 P, [%0], %1, 0x989680;\n\t"
        "@!P bra WL_%=;\n\t"
        "}"
        :: "r"(mb), "r"(par) : "memory");
}

// ---------------- kernel 1: SGEMM  XG[m][n] = A[m][k] @ W[k][n] + bl[n] ----------------
// (R5 version: best measured — 76 regs, occ 37%, fma 63%.)
// M=131072, N=1024, K=256. Tile 128M x 64N, K-tile 16, double-buffered.
#define MT 128
#define NT 64
#define KT 16

__global__ void __launch_bounds__(256) k_xgemm(const float* __restrict__ A,
                                               const float* __restrict__ W,
                                               const float* __restrict__ bl) {
    __shared__ __align__(16) float As[2][KT][MT];
    __shared__ __align__(16) float Bs[2][KT][NT];
    const int tid = threadIdx.x;
    const int m0 = blockIdx.x * MT;
    const int n0 = blockIdx.y * NT;

    const int ar0 = tid >> 2;
    const int akc = (tid & 3) * 4;
    const int bk = tid >> 4;
    const int bn = (tid & 15) * 4;
    const int mt = tid >> 4;
    const int nt = tid & 15;

    const float* Ar0 = A + (size_t)(m0 + ar0) * D_ + akc;
    const float* Ar1 = A + (size_t)(m0 + 64 + ar0) * D_ + akc;
    const float* Wp  = W + (size_t)bk * G4_ + n0 + bn;

    float4 a0 = *(const float4*)(Ar0);
    float4 a1 = *(const float4*)(Ar1);
    float4 b0 = *(const float4*)(Wp);
    #pragma unroll
    for (int i = 0; i < 4; i++) {
        As[0][akc + i][ar0]      = ((const float*)&a0)[i];
        As[0][akc + i][64 + ar0] = ((const float*)&a1)[i];
    }
    *(float4*)&Bs[0][bk][bn] = b0;
    __syncthreads();

    ull acc[4][4];
    #pragma unroll
    for (int p = 0; p < 4; p++)
        #pragma unroll
        for (int n = 0; n < 4; n++) acc[p][n] = 0ull;

    #pragma unroll 1
    for (int kt = 0; kt < D_ / KT; kt++) {
        const int cur = kt & 1, nxt = cur ^ 1;
        if (kt + 1 < D_ / KT) {
            a0 = *(const float4*)(Ar0 + (kt + 1) * KT);
            a1 = *(const float4*)(Ar1 + (kt + 1) * KT);
            b0 = *(const float4*)(Wp + (size_t)(kt + 1) * KT * G4_);
        }
        #pragma unroll
        for (int k = 0; k < KT; k++) {
            const ull* ap = (const ull*)&As[cur][k][mt * 8];
            const float* bp = &Bs[cur][k][nt * 4];
            ull am0 = ap[0], am1 = ap[1], am2 = ap[2], am3 = ap[3];
            #pragma unroll
            for (int n = 0; n < 4; n++) {
                ull bb = pack2(bp[n], bp[n]);
                acc[0][n] = fma2(acc[0][n], am0, bb);
                acc[1][n] = fma2(acc[1][n], am1, bb);
                acc[2][n] = fma2(acc[2][n], am2, bb);
                acc[3][n] = fma2(acc[3][n], am3, bb);
            }
        }
        if (kt + 1 < D_ / KT) {
            #pragma unroll
            for (int i = 0; i < 4; i++) {
                As[nxt][akc + i][ar0]      = ((const float*)&a0)[i];
                As[nxt][akc + i][64 + ar0] = ((const float*)&a1)[i];
            }
            *(float4*)&Bs[nxt][bk][bn] = b0;
            __syncthreads();
        }
    }

    float bias[4];
    #pragma unroll
    for (int n = 0; n < 4; n++) bias[n] = bl[n0 + nt * 4 + n];
    float* Cr = g_XG + (size_t)(m0 + mt * 8) * G4_ + n0 + nt * 4;
    #pragma unroll
    for (int p = 0; p < 4; p++) {
        float e[4], o[4];
        #pragma unroll
        for (int n = 0; n < 4; n++) {
            unpack2(acc[p][n], e[n], o[n]);
            e[n] += bias[n]; o[n] += bias[n];
        }
        *(float4*)(Cr + (size_t)(2 * p) * G4_)     = make_float4(e[0], e[1], e[2], e[3]);
        *(float4*)(Cr + (size_t)(2 * p + 1) * G4_) = make_float4(o[0], o[1], o[2], o[3]);
    }
}

// ---------------- kernel 2: clustered LSTM recurrence (R9 structure, LDS.128 widening) ----------------
// 32 clusters x 8 CTAs, occ 2. Cluster g = batch g. CTA rank r owns j in [32r, 32r+32).
// Thread (w = tid>>5, l = tid&31): K-chunk [32w, 32w+32), hidden j = 32r + l, 4 gates.
// Per-source mbars [src][parity]; __syncthreads each step; warp-0 scalar-reduce epilogue.
// h and streamed-weight loads widened to LDS.128 (same bytes/wavefronts, half the issues).
struct RnnSmem {
    ulonglong2 Wst[8][3][4][32];   // [w][p2][q][l]: .x = pair(20+4p2), .y = pair(22+4p2); 48 KB
    float red[2][8][4][32];        // [par][w][q][l] K-chunk partials, 8 KB
    float hs[2][H_];               // [parity][j] hidden state, 2 KB
    float xg_s[2][4][32];          // [par][q][l] staged XG, 1 KB
    ull   mbar[16];                // [src*2 + parity]
};

__global__ void __launch_bounds__(256, 2) __cluster_dims__(8, 1, 1)
k_rnn(const float* __restrict__ W) {
    extern __shared__ __align__(16) unsigned char smem_raw[];
    RnnSmem* S = (RnnSmem*)smem_raw;

    const int tid = threadIdx.x;
    const int w   = tid >> 5;
    const int l   = tid & 31;
    const int r   = blockIdx.x & 7;
    const int g   = blockIdx.x >> 3;
    const int kbase = w * 32;
    const int j   = r * 32 + l;

    // stationary weights: 40 reg pairs (10 per gate) + 24 streamed pairs (6 per gate, paired)
    ull wreg[40];
    #pragma unroll
    for (int q = 0; q < 4; q++) {
        int n = q * 256 + j;
        #pragma unroll
        for (int p = 0; p < 10; p++) {
            int k = kbase + 2 * p;
            wreg[q * 10 + p] = pack2(W[(size_t)(D_ + k) * G4_ + n],
                                     W[(size_t)(D_ + k + 1) * G4_ + n]);
        }
        #pragma unroll
        for (int p2 = 0; p2 < 3; p2++) {
            int k = kbase + 20 + 4 * p2;
            ulonglong2 v;
            v.x = pack2(W[(size_t)(D_ + k)     * G4_ + n], W[(size_t)(D_ + k + 1) * G4_ + n]);
            v.y = pack2(W[(size_t)(D_ + k + 2) * G4_ + n], W[(size_t)(D_ + k + 3) * G4_ + n]);
            S->Wst[w][p2][q][l] = v;
        }
    }
    for (int i = tid; i < H_; i += 256) S->hs[0][i] = 0.f;
    float c_state = 0.f;   // valid in warp 0

    const unsigned sbase  = smem_u32(S);
    const unsigned hs_off = (unsigned)((char*)&S->hs[0][0] - (char*)S);
    const unsigned mb_off = (unsigned)((char*)&S->mbar[0] - (char*)S);

    if (tid == 0) {
        #pragma unroll
        for (int i = 0; i < 16; i++) {
            asm volatile("mbarrier.init.shared.b64 [%0], 1;"
                         :: "r"(sbase + mb_off + i * 8) : "memory");
        }
        #pragma unroll
        for (int i = 0; i < 16; i++) {
            asm volatile("mbarrier.arrive.expect_tx.shared.b64 _, [%0], 128;"
                         :: "r"(sbase + mb_off + i * 8) : "memory");
        }
    }
    __syncthreads();
    asm volatile("barrier.cluster.arrive.aligned;" ::: "memory");
    asm volatile("barrier.cluster.wait.aligned;"   ::: "memory");

    unsigned rbase[8];
    #pragma unroll
    for (int d = 0; d < 8; d++)
        asm("mapa.shared::cluster.u32 %0, %1, %2;" : "=r"(rbase[d]) : "r"(sbase), "r"(d));

    // XG stream: warp w (w<4) covers gate w: XG[g][t][w*256 + j], one 128B line/warp/step
    const float* xgp = g_XG + ((size_t)g * T_) * G4_ + w * 256 + j;
    float xv = (tid < 128) ? __ldcs(xgp) : 0.f;

    #pragma unroll 1
    for (int t = 0; t < T_; ++t) {
        const int par = t & 1;

        // stage XG + prefetch next (safe before the wait: syncthreads(t+1) provides the lap edge)
        if (tid < 128) {
            S->xg_s[par][w][l] = xv;
            if (t + 1 < T_) xv = __ldcs(xgp + (size_t)(t + 1) * G4_);
        }

        // wait only for the source rank whose h slice this warp consumes
        if (t > 0) {
            const unsigned moff = sbase + mb_off + (unsigned)((w * 2 + ((t - 1) & 1)) * 8);
            mbar_wait_cluster(moff, ((t - 1) >> 1) & 1);
            if (l == 0) {
                asm volatile("mbarrier.arrive.expect_tx.shared.b64 _, [%0], 128;"
                             :: "r"(moff) : "memory");
            }
        }

        const ull* hp = (const ull*)&S->hs[par][kbase];
        ull acc0 = 0, acc1 = 0, acc2 = 0, acc3 = 0;

        // register-weight half: 5 LDS.128 h broadcasts
        #pragma unroll
        for (int p2 = 0; p2 < 5; p2++) {
            ulonglong2 h2 = *(const ulonglong2*)&hp[2 * p2];
            acc0 = fma2(acc0, wreg[2 * p2],      h2.x); acc0 = fma2(acc0, wreg[2 * p2 + 1],      h2.y);
            acc1 = fma2(acc1, wreg[10 + 2 * p2], h2.x); acc1 = fma2(acc1, wreg[10 + 2 * p2 + 1], h2.y);
            acc2 = fma2(acc2, wreg[20 + 2 * p2], h2.x); acc2 = fma2(acc2, wreg[20 + 2 * p2 + 1], h2.y);
            acc3 = fma2(acc3, wreg[30 + 2 * p2], h2.x); acc3 = fma2(acc3, wreg[30 + 2 * p2 + 1], h2.y);
        }
        // streamed-weight half: 3 LDS.128 h broadcasts + 12 LDS.128 weights
        const ulonglong2* wst = &S->Wst[w][0][0][l];
        #pragma unroll
        for (int p2 = 0; p2 < 3; p2++) {
            ulonglong2 h2 = *(const ulonglong2*)&hp[10 + 2 * p2];
            ulonglong2 w0 = wst[p2 * 128 + 0];
            ulonglong2 w1 = wst[p2 * 128 + 32];
            ulonglong2 w2 = wst[p2 * 128 + 64];
            ulonglong2 w3 = wst[p2 * 128 + 96];
            acc0 = fma2(acc0, w0.x, h2.x); acc0 = fma2(acc0, w0.y, h2.y);
            acc1 = fma2(acc1, w1.x, h2.x); acc1 = fma2(acc1, w1.y, h2.y);
            acc2 = fma2(acc2, w2.x, h2.x); acc2 = fma2(acc2, w2.y, h2.y);
            acc3 = fma2(acc3, w3.x, h2.x); acc3 = fma2(acc3, w3.y, h2.y);
        }

        {
            float ax, ay;
            unpack2(acc0, ax, ay); S->red[par][w][0][l] = ax + ay;
            unpack2(acc1, ax, ay); S->red[par][w][1][l] = ax + ay;
            unpack2(acc2, ax, ay); S->red[par][w][2][l] = ax + ay;
            unpack2(acc3, ax, ay); S->red[par][w][3][l] = ax + ay;
        }
        __syncthreads();

        // warp 0: reduce over 8 K-chunks, activations, per-source DSMEM broadcast
        if (w == 0) {
            float gsum[4];
            #pragma unroll
            for (int q = 0; q < 4; q++) {
                float s = S->xg_s[par][q][l];
                #pragma unroll
                for (int kh2 = 0; kh2 < 8; kh2++) s += S->red[par][kh2][q][l];
                gsum[q] = s;
            }
            c_state = sigf(gsum[2] + 1.f) * c_state + sigf(gsum[0]) * tanh_f(gsum[1]);
            float h = sigf(gsum[3]) * tanh_f(c_state);
            unsigned hbits = __float_as_uint(h);

            if (t + 1 < T_) {
                const unsigned dst_off = hs_off + (unsigned)((((t + 1) & 1) * H_ + j) * 4);
                const unsigned mbr_off = mb_off + (unsigned)((r * 2 + par) * 8);
                #pragma unroll
                for (int d = 0; d < 8; d++) {
                    asm volatile(
                        "st.async.weak.shared::cluster.mbarrier::complete_tx::bytes.u32 [%0], %1, [%2];"
                        :: "r"(rbase[d] + dst_off), "r"(hbits), "r"(rbase[d] + mbr_off)
                        : "memory");
                }
            } else {
                g_h[g * H_ + j] = h;
            }
        }
    }
    // no drain needed: every issued store is consumed by a receiver wait before exit
}

// ---------------- kernel 3: out = (h @ Wfc + bfc) @ Wout + bout ----------------
__global__ void __launch_bounds__(256) k_fc(const float* __restrict__ Wfc,
                                            const float* __restrict__ bfc,
                                            const float* __restrict__ Wout,
                                            const float* __restrict__ bout,
                                            float* __restrict__ out) {
    __shared__ float tmp[H_];
    int b = blockIdx.x;
    int jj = threadIdx.x;
    const float* h = &g_h[b * H_];
    float s = bfc[jj];
    #pragma unroll 8
    for (int k = 0; k < H_; k++) s += h[k] * Wfc[(size_t)k * H_ + jj];
    tmp[jj] = s;
    __syncthreads();
    if (jj < HOR_) {
        float o = bout[jj];
        #pragma unroll 8
        for (int k = 0; k < H_; k++) o += tmp[k] * Wout[(size_t)k * HOR_ + jj];
        out[b * HOR_ + jj] = o;
    }
}

// ---------------- launch ----------------
extern "C" void kernel_launch(void* const* d_in, const int* in_sizes, int n_in,
                              void* d_out, int out_size) {
    const float* x      = (const float*)d_in[0];
    const float* W_lstm = (const float*)d_in[1];
    const float* b_lstm = (const float*)d_in[2];
    const float* W_fc   = (const float*)d_in[3];
    const float* b_fc   = (const float*)d_in[4];
    const float* W_out  = (const float*)d_in[5];
    const float* b_out  = (const float*)d_in[6];
    float* out = (float*)d_out;

    cudaFuncSetAttribute(k_rnn, cudaFuncAttributeMaxDynamicSharedMemorySize,
                         (int)sizeof(RnnSmem));

    k_xgemm<<<dim3((B_ * T_) / MT, G4_ / NT), 256>>>(x, W_lstm, b_lstm);
    k_rnn<<<256, 256, sizeof(RnnSmem)>>>(W_lstm);
    k_fc<<<B_, 256>>>(W_fc, b_fc, W_out, b_out, out);
}